// round 17
// baseline (speedup 1.0000x reference)
#include <cuda_runtime.h>
#include <cuda_fp16.h>
#include <cstdint>

// Causal self-attention head as THREE kernels:
//  0) w_prep: [Wk|Wq|Wv] fp32 -> fp16 chunk-major (kCH=64) staging
//  1) proj_kernel: KQV GEMM, kCH=64, dist-2 x prefetch, cp.async W 3-ring, occ 2
//  2) attn_kernel: flash-style attention, 2 batches/CTA with cross-batch
//     causal pairing (warp w does tile w of batch A + tile 7-w of batch B)
// B=1024, T=128, C=384, HS=64, fp32 in/out.

static constexpr int kT  = 128;
static constexpr int kC  = 384;
static constexpr int kHS = 64;
static constexpr int kCH = 64;              // C-chunk (floats)
static constexpr int kNCH = kC / kCH;       // 6
static constexpr int kNW  = 192;            // 3*64 combined output cols

// fp16 scratch: K,Q [b][t][h]; Vt [b][h][t]
__device__ __half g_K [1024 * 128 * 64];
__device__ __half g_Q [1024 * 128 * 64];
__device__ __half g_Vt[1024 * 64 * 128];
// fp16 W chunk-major: [chunk][n][c]  (n=0..191, c=0..63)
__device__ __half g_Wh[kNCH * kNW * kCH];

// ---- proj_kernel smem (words) ----
static constexpr int LDXW   = 36;                    // 32 half2-words data + 4 pad
static constexpr int XBUF_W = 64  * LDXW;            // 2304
static constexpr int WBUF_W = kNW * LDXW;            // 6912
static constexpr int XB0 = 0;
static constexpr int XB1 = XBUF_W;                   // 2304
static constexpr int WB0 = 2 * XBUF_W;               // 4608
static constexpr int SMEM1_WORDS = WB0 + 3 * WBUF_W; // 25344
static constexpr int SMEM1_BYTES = SMEM1_WORDS * 4;  // 101376

// ---- attn_kernel smem (words), two batch copies ----
static constexpr int LDH  = 36;
static constexpr int LDVT = 68;
static constexpr int W2_Q  = 0;
static constexpr int W2_K  = W2_Q + kT * LDH;        // 4608
static constexpr int W2_VT = W2_K + kT * LDH;        // 9216
static constexpr int SMB   = W2_VT + kHS * LDVT;     // 13568 words per batch
static constexpr int SMEM2_BYTES = 2 * SMB * 4;      // 108544

// ---------------- helpers ----------------
__device__ __forceinline__ uint32_t pkh2(float a, float b) {
    __half2 h = __floats2half2_rn(a, b);
    return *(uint32_t*)&h;
}
__device__ __forceinline__ uint32_t s2u(const void* p) {
    uint32_t a;
    asm("{ .reg .u64 t; cvta.to.shared.u64 t, %1; cvt.u32.u64 %0, t; }" : "=r"(a) : "l"(p));
    return a;
}
__device__ __forceinline__ void mma_f16(float c[4], const uint32_t a[4],
                                        uint32_t b0, uint32_t b1) {
    asm volatile(
        "mma.sync.aligned.m16n8k16.row.col.f32.f16.f16.f32 "
        "{%0,%1,%2,%3}, {%4,%5,%6,%7}, {%8,%9}, {%0,%1,%2,%3};"
        : "+f"(c[0]), "+f"(c[1]), "+f"(c[2]), "+f"(c[3])
        : "r"(a[0]), "r"(a[1]), "r"(a[2]), "r"(a[3]), "r"(b0), "r"(b1));
}
__device__ __forceinline__ void ldmx4(uint32_t& r0, uint32_t& r1,
                                      uint32_t& r2, uint32_t& r3, uint32_t addr) {
    asm volatile("ldmatrix.sync.aligned.m8n8.x4.shared.b16 {%0,%1,%2,%3}, [%4];"
                 : "=r"(r0), "=r"(r1), "=r"(r2), "=r"(r3) : "r"(addr));
}
__device__ __forceinline__ void cpa16(uint32_t dst, const void* src) {
    asm volatile("cp.async.cg.shared.global [%0], [%1], 16;" :: "r"(dst), "l"(src) : "memory");
}

// ================= Kernel 0: W fp32 -> fp16 chunk-major =================
__global__ void __launch_bounds__(256)
w_prep(const float* __restrict__ Wk,
       const float* __restrict__ Wq,
       const float* __restrict__ Wv) {
    const int g = (blockIdx.x * 256 + threadIdx.x) * 4;   // 0..73724
    const int n = g / kC;
    const int c = g % kC;
    const float* Wm = (n < 64) ? (Wk + n * kC)
                      : (n < 128) ? (Wq + (n - 64) * kC)
                                  : (Wv + (n - 128) * kC);
    float4 v = *(const float4*)(Wm + c);
    const int cb = c / kCH, cc = c % kCH;
    uint32_t* dst = (uint32_t*)(g_Wh + (cb * kNW + n) * kCH + cc);
    dst[0] = pkh2(v.x, v.y);
    dst[1] = pkh2(v.z, v.w);
}

// ================= Kernel 1: projection GEMM (unchanged from R16) =====
__global__ void __launch_bounds__(256, 2)
proj_kernel(const float* __restrict__ x) {
    extern __shared__ uint32_t sm[];
    const uint32_t smu = s2u(sm);
    const int tid  = threadIdx.x;
    const int wid  = tid >> 5;
    const int lane = tid & 31;
    const int g4   = lane >> 2;
    const int t4   = lane & 3;
    const int l15  = lane & 15;
    const int l16w = (lane >> 4) * 4;
    const int wm   = wid & 1;
    const int wn   = wid >> 1;
    const int b    = blockIdx.x >> 1;
    const int hm   = blockIdx.x & 1;
    const float* xb = x + (size_t)b * (kT * kC) + hm * 64 * kC;

    const int xt[4] = { (tid + 0) >> 4, (tid + 256) >> 4, (tid + 512) >> 4, (tid + 768) >> 4 };
    const int xf = tid & 15;
    float4 xr[2][4];

    // ---- prologue ----
#pragma unroll
    for (int r = 0; r < 4; ++r)
        xr[1][r] = *(const float4*)(xb + xt[r] * kC + 0 * kCH + xf * 4);
#pragma unroll
    for (int r = 0; r < 4; ++r)
        *(uint2*)(sm + XB0 + xt[r] * LDXW + xf * 2) =
            make_uint2(pkh2(xr[1][r].x, xr[1][r].y), pkh2(xr[1][r].z, xr[1][r].w));
#pragma unroll
    for (int r = 0; r < 4; ++r)
        xr[1][r] = *(const float4*)(xb + xt[r] * kC + 1 * kCH + xf * 4);
#pragma unroll
    for (int r = 0; r < 6; ++r) {
        int idx = tid + 256 * r, n = idx >> 3, q = idx & 7;
        cpa16(smu + 4u * (uint32_t)(WB0 + n * LDXW + q * 4),
              g_Wh + (0 * kNW + n) * kCH + q * 8);
    }
    asm volatile("cp.async.commit_group;" ::: "memory");
#pragma unroll
    for (int r = 0; r < 6; ++r) {
        int idx = tid + 256 * r, n = idx >> 3, q = idx & 7;
        cpa16(smu + 4u * (uint32_t)(WB0 + WBUF_W + n * LDXW + q * 4),
              g_Wh + (1 * kNW + n) * kCH + q * 8);
    }
    asm volatile("cp.async.commit_group;" ::: "memory");
    asm volatile("cp.async.wait_group 1;" ::: "memory");
    __syncthreads();

    float c[2][6][4];
#pragma unroll
    for (int mt = 0; mt < 2; ++mt)
#pragma unroll
        for (int nt = 0; nt < 6; ++nt)
#pragma unroll
            for (int j = 0; j < 4; ++j) c[mt][nt][j] = 0.f;

    for (int cb = 0; cb < kNCH; ++cb) {
        const int p = cb & 1;
        if (cb <= 4) {
            const int s = p ^ 1;
            uint32_t* bx = sm + (p ? XB0 : XB1);
#pragma unroll
            for (int r = 0; r < 4; ++r)
                *(uint2*)(bx + xt[r] * LDXW + xf * 2) =
                    make_uint2(pkh2(xr[s][r].x, xr[s][r].y), pkh2(xr[s][r].z, xr[s][r].w));
        }
        if (cb <= 3) {
            const int s = p;
            const int cbase = (cb + 2) * kCH;
#pragma unroll
            for (int r = 0; r < 4; ++r)
                xr[s][r] = *(const float4*)(xb + xt[r] * kC + cbase + xf * 4);
        }
        if (cb <= 3) {
            const __half* wsrc = g_Wh + (cb + 2) * (kNW * kCH);
            const uint32_t wdst = smu + 4u * (uint32_t)(WB0 + ((cb + 2) % 3) * WBUF_W);
#pragma unroll
            for (int r = 0; r < 6; ++r) {
                int idx = tid + 256 * r, n = idx >> 3, q = idx & 7;
                cpa16(wdst + 4u * (uint32_t)(n * LDXW + q * 4), wsrc + n * kCH + q * 8);
            }
            asm volatile("cp.async.commit_group;" ::: "memory");
        }
        {
            const uint32_t bx = smu + 4u * (uint32_t)(p ? XB1 : XB0);
            const uint32_t bw = smu + 4u * (uint32_t)(WB0 + (cb % 3) * WBUF_W);
#pragma unroll
            for (int kk = 0; kk < 4; ++kk) {
                uint32_t a[2][4];
#pragma unroll
                for (int mt = 0; mt < 2; ++mt)
                    ldmx4(a[mt][0], a[mt][1], a[mt][2], a[mt][3],
                          bx + 4 * ((wm * 32 + mt * 16 + l15) * LDXW + kk * 8 + l16w));
#pragma unroll
                for (int np = 0; np < 3; ++np) {
                    uint32_t r0, r1, r2, r3;
                    ldmx4(r0, r1, r2, r3,
                          bw + 4 * ((wn * 48 + np * 16 + l15) * LDXW + kk * 8 + l16w));
                    mma_f16(c[0][2 * np    ], a[0], r0, r2);
                    mma_f16(c[1][2 * np    ], a[1], r0, r2);
                    mma_f16(c[0][2 * np + 1], a[0], r1, r3);
                    mma_f16(c[1][2 * np + 1], a[1], r1, r3);
                }
            }
        }
        if (cb <= 3) {
            asm volatile("cp.async.wait_group 1;" ::: "memory");
        } else if (cb == 4) {
            asm volatile("cp.async.wait_group 0;" ::: "memory");
        }
        __syncthreads();
    }

    const size_t bo = (size_t)b * (kT * kHS);
#pragma unroll
    for (int mt = 0; mt < 2; ++mt) {
        int r0 = hm * 64 + wm * 32 + mt * 16 + g4, r1 = r0 + 8;
#pragma unroll
        for (int nt = 0; nt < 6; ++nt) {
            int gc = wn * 48 + nt * 8 + 2 * t4;
            int m = gc >> 6, col = gc & 63;
            if (m < 2) {
                __half* base = (m == 0 ? g_K : g_Q) + bo;
                *(uint32_t*)(base + r0 * kHS + col) = pkh2(c[mt][nt][0], c[mt][nt][1]);
                *(uint32_t*)(base + r1 * kHS + col) = pkh2(c[mt][nt][2], c[mt][nt][3]);
            } else {
                __half* vb = g_Vt + bo;
                vb[(col    ) * kT + r0] = __float2half_rn(c[mt][nt][0]);
                vb[(col + 1) * kT + r0] = __float2half_rn(c[mt][nt][1]);
                vb[(col    ) * kT + r1] = __float2half_rn(c[mt][nt][2]);
                vb[(col + 1) * kT + r1] = __float2half_rn(c[mt][nt][3]);
            }
        }
    }
}

// ================= Kernel 2: attention, 2 batches/CTA, balanced =========
// Grid 512. CTA handles batches {2B, 2B+1}. Warp w computes row-tile w of
// batch A, then row-tile 7-w of batch B: (w+1)+(8-w)=9 tile-units per warp.
__global__ void __launch_bounds__(256, 2)
attn_kernel(float* __restrict__ out) {
    extern __shared__ uint32_t sm[];
    const uint32_t smu = s2u(sm);
    const int tid  = threadIdx.x;
    const int w    = tid >> 5;
    const int lane = tid & 31;
    const int g4   = lane >> 2;
    const int t4   = lane & 3;
    const int l15  = lane & 15;
    const int l16w = (lane >> 4) * 4;

    // cooperative load of both batches' Q, K, Vt into smem
#pragma unroll
    for (int it = 0; it < 2; ++it) {
        const size_t bb = (size_t)(blockIdx.x * 2 + it) * (kT * kHS);
        const uint4* gq = (const uint4*)(g_Q  + bb);
        const uint4* gk = (const uint4*)(g_K  + bb);
        const uint4* gv = (const uint4*)(g_Vt + bb);
        uint32_t* s = sm + it * SMB;
#pragma unroll
        for (int r = 0; r < 4; ++r) {
            int idx = tid + 256 * r, t = idx >> 3, q = idx & 7;
            *(uint4*)(s + W2_Q + t * LDH + q * 4) = gq[t * 8 + q];
            *(uint4*)(s + W2_K + t * LDH + q * 4) = gk[t * 8 + q];
        }
#pragma unroll
        for (int r = 0; r < 4; ++r) {
            int idx = tid + 256 * r, h = idx >> 4, q = idx & 15;
            *(uint4*)(s + W2_VT + h * LDVT + q * 4) = gv[h * 16 + q];
        }
    }
    __syncthreads();

#pragma unroll 1
    for (int it = 0; it < 2; ++it) {
        const int tile = (it == 0) ? w : 7 - w;         // balanced pairing
        const uint32_t sb = smu + 4u * (uint32_t)(it * SMB);
        const int bb = blockIdx.x * 2 + it;

        // ---- S = Q @ K^T for rows [16*tile, 16*tile+16), col tiles np <= tile
        float cs[16][4];
#pragma unroll
        for (int nt = 0; nt < 16; ++nt)
#pragma unroll
            for (int j = 0; j < 4; ++j) cs[nt][j] = 0.f;

#pragma unroll
        for (int kk = 0; kk < 4; ++kk) {
            uint32_t a[4];
            ldmx4(a[0], a[1], a[2], a[3],
                  sb + 4 * (W2_Q + (tile * 16 + l15) * LDH + kk * 8 + l16w));
#pragma unroll
            for (int np = 0; np < 8; ++np)
                if (np <= tile) {
                    uint32_t r0, r1, r2, r3;
                    ldmx4(r0, r1, r2, r3,
                          sb + 4 * (W2_K + (np * 16 + l15) * LDH + kk * 8 + l16w));
                    mma_f16(cs[2 * np    ], a, r0, r2);
                    mma_f16(cs[2 * np + 1], a, r1, r3);
                }
        }

        // ---- warp-local causal softmax ----
        const float scale = 0.05103103630798288f;    // 384^-0.5
#pragma unroll
        for (int h = 0; h < 2; ++h) {
            const int row = tile * 16 + g4 + 8 * h;
            float m = -1e30f;
#pragma unroll
            for (int nt = 0; nt < 16; ++nt)
                if (nt < 2 * tile + 2)
#pragma unroll
                    for (int j = 0; j < 2; ++j) {
                        int col = nt * 8 + 2 * t4 + j;
                        float f = cs[nt][2 * h + j] * scale;
                        if (col > row) f = -1e30f;
                        cs[nt][2 * h + j] = f;
                        m = fmaxf(m, f);
                    }
            m = fmaxf(m, __shfl_xor_sync(0xffffffffu, m, 1));
            m = fmaxf(m, __shfl_xor_sync(0xffffffffu, m, 2));
            float s = 0.f;
#pragma unroll
            for (int nt = 0; nt < 16; ++nt)
                if (nt < 2 * tile + 2)
#pragma unroll
                    for (int j = 0; j < 2; ++j) {
                        float e = __expf(cs[nt][2 * h + j] - m);
                        cs[nt][2 * h + j] = e;
                        s += e;
                    }
            s += __shfl_xor_sync(0xffffffffu, s, 1);
            s += __shfl_xor_sync(0xffffffffu, s, 2);
            const float inv = 1.0f / s;
#pragma unroll
            for (int nt = 0; nt < 16; ++nt)
                if (nt < 2 * tile + 2)
#pragma unroll
                    for (int j = 0; j < 2; ++j) cs[nt][2 * h + j] *= inv;
        }

        // ---- pack P into A-fragments (half2) ----
        uint32_t pa[8][4];
#pragma unroll
        for (int kk = 0; kk < 8; ++kk) {
            pa[kk][0] = pkh2(cs[2 * kk    ][0], cs[2 * kk    ][1]);
            pa[kk][1] = pkh2(cs[2 * kk    ][2], cs[2 * kk    ][3]);
            pa[kk][2] = pkh2(cs[2 * kk + 1][0], cs[2 * kk + 1][1]);
            pa[kk][3] = pkh2(cs[2 * kk + 1][2], cs[2 * kk + 1][3]);
        }

        // ---- out = P @ V, kk <= tile ----
        float co[8][4];
#pragma unroll
        for (int nt = 0; nt < 8; ++nt)
#pragma unroll
            for (int j = 0; j < 4; ++j) co[nt][j] = 0.f;

#pragma unroll
        for (int kk = 0; kk < 8; ++kk)
            if (kk <= tile) {
#pragma unroll
                for (int ht = 0; ht < 4; ++ht) {
                    uint32_t r0, r1, r2, r3;
                    ldmx4(r0, r1, r2, r3,
                          sb + 4 * (W2_VT + (ht * 16 + l15) * LDVT + kk * 8 + l16w));
                    mma_f16(co[2 * ht    ], pa[kk], r0, r2);
                    mma_f16(co[2 * ht + 1], pa[kk], r1, r3);
                }
            }

        float* ob = out + (size_t)bb * (kT * kHS);
        const int r0 = tile * 16 + g4, r1 = r0 + 8;
#pragma unroll
        for (int nt = 0; nt < 8; ++nt) {
            int h0 = nt * 8 + 2 * t4;
            *(float2*)(ob + r0 * kHS + h0) = make_float2(co[nt][0], co[nt][1]);
            *(float2*)(ob + r1 * kHS + h0) = make_float2(co[nt][2], co[nt][3]);
        }
    }
}

extern "C" void kernel_launch(void* const* d_in, const int* in_sizes, int n_in,
                              void* d_out, int out_size) {
    const float* x  = (const float*)d_in[0];
    const float* Wk = (const float*)d_in[1];
    const float* Wq = (const float*)d_in[2];
    const float* Wv = (const float*)d_in[3];
    float* out = (float*)d_out;

    const int B = in_sizes[0] / (kT * kC);   // 1024
    cudaFuncSetAttribute(proj_kernel,
                         cudaFuncAttributeMaxDynamicSharedMemorySize, SMEM1_BYTES);
    cudaFuncSetAttribute(attn_kernel,
                         cudaFuncAttributeMaxDynamicSharedMemorySize, SMEM2_BYTES);
    w_prep<<<72, 256>>>(Wk, Wq, Wv);
    proj_kernel<<<2 * B, 256, SMEM1_BYTES>>>(x);
    attn_kernel<<<B / 2, 256, SMEM2_BYTES>>>(out);
}